// round 1
// baseline (speedup 1.0000x reference)
#include <cuda_runtime.h>
#include <cstdint>

// Problem constants
#define CO_   1024
#define CI_   1024
#define KTOT  9216           // CI_ * 9
#define NXEL  6422528        // 8*1024*4*14*14
#define NIDX  6272           // 2*4*4*196
#define STR_S 802816         // 1024*784
#define STR_N 3211264        // 4*STR_S

#define BM 128
#define BN 128
#define BK 16
#define KTILES (KTOT / BK)   // 576
#define AS_LD 20
#define BS_LD 136

// Scratch: TF32-rounded, W permuted so k' = tap*1024 + ci
__device__ __align__(128) float g_Wp[CO_ * KTOT];
__device__ __align__(128) float g_xt[NXEL];

__device__ __forceinline__ uint32_t f2tf32(float f) {
    uint32_t v;
    asm("cvt.rna.tf32.f32 %0, %1;" : "=r"(v) : "f"(f));
    return v;
}

__global__ void prep_w_kernel(const float* __restrict__ W) {
    int i = blockIdx.x * blockDim.x + threadIdx.x;
    if (i >= CO_ * KTOT) return;
    int co = i / KTOT;
    int k  = i - co * KTOT;
    int ci = k / 9;
    int rr = k - ci * 9;
    g_Wp[co * KTOT + rr * CI_ + ci] = __uint_as_float(f2tf32(W[i]));
}

__global__ void prep_x_kernel(const float* __restrict__ x) {
    int i = blockIdx.x * blockDim.x + threadIdx.x;
    if (i >= NXEL) return;
    g_xt[i] = __uint_as_float(f2tf32(x[i]));
}

__device__ __forceinline__ void cp_async16(uint32_t dst, const void* src) {
    asm volatile("cp.async.cg.shared.global [%0], [%1], 16;" :: "r"(dst), "l"(src));
}
__device__ __forceinline__ void cp_async4z(uint32_t dst, const void* src, int src_bytes) {
    // zfill when src_bytes == 0
    asm volatile("cp.async.ca.shared.global [%0], [%1], 4, %2;" :: "r"(dst), "l"(src), "r"(src_bytes));
}
__device__ __forceinline__ void cp_commit() {
    asm volatile("cp.async.commit_group;");
}
template <int N>
__device__ __forceinline__ void cp_wait() {
    asm volatile("cp.async.wait_group %0;" :: "n"(N));
}

__device__ __forceinline__ void mma_tf32(float* d, const uint32_t* a, const uint32_t* b) {
    asm volatile(
        "mma.sync.aligned.m16n8k8.row.col.f32.tf32.tf32.f32 "
        "{%0,%1,%2,%3}, {%4,%5,%6,%7}, {%8,%9}, {%0,%1,%2,%3};"
        : "+f"(d[0]), "+f"(d[1]), "+f"(d[2]), "+f"(d[3])
        : "r"(a[0]), "r"(a[1]), "r"(a[2]), "r"(a[3]), "r"(b[0]), "r"(b[1]));
}

__global__ __launch_bounds__(256, 1)
void conv_gemm_kernel(const float* __restrict__ x, float* __restrict__ out) {
    __shared__ __align__(16) float As[2][BM * AS_LD];   // [m][k], padded
    __shared__ __align__(16) float Bs[2][BK * BS_LD];   // [k][n], padded

    const int tid  = threadIdx.x;
    const int lane = tid & 31;
    const int warp = tid >> 5;
    const int wm   = warp & 1;   // 2 warp-tiles along M (64 each)
    const int wn   = warp >> 1;  // 4 warp-tiles along N (32 each)
    const int r    = lane >> 2;  // groupID
    const int c    = lane & 3;   // threadID in group

    const int tileM = blockIdx.y * BM;
    const int tileN = blockIdx.x * BN;

    // ---- B gather precompute: this thread owns column n_local, k rows {klo, klo+2, ...} ----
    const int nl   = tid & 127;
    const int nidx = tileN + nl;
    const int nn = nidx / 3136;
    const int r1 = nidx - nn * 3136;
    const int ss = r1 / 784;
    const int r2 = r1 - ss * 784;
    const int tt = r2 / 196;
    const int pp = r2 - tt * 196;
    const int D0 = nn * STR_N + pp + (ss - 1) * STR_S + (tt - 1) * 196;
    const int klo   = tid >> 7;            // 0 or 1
    const int kl784 = klo * 784;

    // ---- A load precompute: two 16B slots per thread ----
    const int am0 = tid >> 2;              // 0..63
    const int am1 = am0 + 64;
    const int aj  = (tid & 3) * 4;

    const uint32_t as_base = (uint32_t)__cvta_generic_to_shared(&As[0][0]);
    const uint32_t bs_base = (uint32_t)__cvta_generic_to_shared(&Bs[0][0]);
    const uint32_t as_stride = BM * AS_LD * 4;
    const uint32_t bs_stride = BK * BS_LD * 4;

    float acc[4][4][4];
    #pragma unroll
    for (int mi = 0; mi < 4; mi++)
        #pragma unroll
        for (int ni = 0; ni < 4; ni++)
            #pragma unroll
            for (int q = 0; q < 4; q++) acc[mi][ni][q] = 0.0f;

    auto load_tiles = [&](int kt, int buf) {
        const int k0 = kt * BK;
        // A tile: W-permuted, fully contiguous rows
        const float* ap = g_Wp + (size_t)(tileM + am0) * KTOT + k0 + aj;
        uint32_t ad = as_base + buf * as_stride + (uint32_t)(am0 * AS_LD + aj) * 4;
        cp_async16(ad, ap);
        cp_async16(ad + (uint32_t)(64 * AS_LD) * 4, ap + (size_t)64 * KTOT);
        // B tile: tap (rr) is constant across this K-tile (1024 % 16 == 0)
        const int rr = k0 >> 10;
        const int ds = (rr * 11) >> 5;       // rr / 3 for rr in [0,9)
        const int dt = rr - ds * 3;
        const bool vs = (unsigned)(ss - 1 + ds) < 4u;
        const bool vt = (unsigned)(tt - 1 + dt) < 4u;
        const int pred = (vs && vt) ? 4 : 0;
        const int ci_base = k0 & 1023;
        const int AB = D0 + ds * STR_S + dt * 196 + ci_base * 784 + kl784;
        const float* bp = g_xt + (pred ? AB : 0);
        uint32_t bd = bs_base + buf * bs_stride + (uint32_t)(klo * BS_LD + nl) * 4;
        #pragma unroll
        for (int i = 0; i < 8; i++) {
            cp_async4z(bd + (uint32_t)(i * 2 * BS_LD) * 4, bp + i * (2 * 784), pred);
        }
    };

    auto compute = [&](int buf) {
        #pragma unroll
        for (int ks = 0; ks < 2; ks++) {
            const int kk = ks * 8;
            uint32_t afr[4][4];
            uint32_t bfr[4][2];
            const float* a = &As[buf][0];
            const float* b = &Bs[buf][0];
            #pragma unroll
            for (int mi = 0; mi < 4; mi++) {
                const int m = wm * 64 + mi * 16;
                afr[mi][0] = __float_as_uint(a[(m + r    ) * AS_LD + kk + c    ]);
                afr[mi][1] = __float_as_uint(a[(m + r + 8) * AS_LD + kk + c    ]);
                afr[mi][2] = __float_as_uint(a[(m + r    ) * AS_LD + kk + c + 4]);
                afr[mi][3] = __float_as_uint(a[(m + r + 8) * AS_LD + kk + c + 4]);
            }
            #pragma unroll
            for (int ni = 0; ni < 4; ni++) {
                const int n = wn * 32 + ni * 8;
                bfr[ni][0] = __float_as_uint(b[(kk + c    ) * BS_LD + n + r]);
                bfr[ni][1] = __float_as_uint(b[(kk + c + 4) * BS_LD + n + r]);
            }
            #pragma unroll
            for (int mi = 0; mi < 4; mi++)
                #pragma unroll
                for (int ni = 0; ni < 4; ni++)
                    mma_tf32(acc[mi][ni], afr[mi], bfr[ni]);
        }
    };

    load_tiles(0, 0);
    cp_commit();

    for (int kt = 0; kt < KTILES; kt++) {
        const int buf = kt & 1;
        if (kt + 1 < KTILES) {
            load_tiles(kt + 1, buf ^ 1);
            cp_commit();
            cp_wait<1>();
        } else {
            cp_wait<0>();
        }
        __syncthreads();
        compute(buf);
        __syncthreads();
    }

    // ---- Epilogue: residual add from original fp32 x, write out ----
    #pragma unroll
    for (int ni = 0; ni < 4; ni++) {
        #pragma unroll
        for (int jj = 0; jj < 2; jj++) {
            const int col = tileN + wn * 32 + ni * 8 + 2 * c + jj;
            const int n2 = col / 3136; const int q1 = col - n2 * 3136;
            const int s2 = q1 / 784;   const int q2 = q1 - s2 * 784;
            const int t2 = q2 / 196;   const int p2 = q2 - t2 * 196;
            const int ooff = (n2 * 4 + s2) * STR_S + t2 * 196 + p2;
            #pragma unroll
            for (int mi = 0; mi < 4; mi++) {
                const int row0 = tileM + wm * 64 + mi * 16 + r;
                const int a0i = row0 * 784 + ooff;
                const int a1i = a0i + 8 * 784;
                out[a0i] = acc[mi][ni][jj    ] + x[a0i];
                out[a1i] = acc[mi][ni][2 + jj] + x[a1i];
            }
        }
    }
}

extern "C" void kernel_launch(void* const* d_in, const int* in_sizes, int n_in,
                              void* d_out, int out_size) {
    const float* x = (const float*)d_in[0];
    const float* W = (const float*)d_in[1];
    // Robustness: identify by element count (x: 6,422,528; W: 9,437,184)
    if (n_in >= 2 && in_sizes[0] == CO_ * KTOT) {
        const float* tmp = x; x = W; W = tmp;
    }

    prep_w_kernel<<<(CO_ * KTOT + 255) / 256, 256>>>(W);
    prep_x_kernel<<<(NXEL + 255) / 256, 256>>>(x);

    dim3 grid(NIDX / BN, CO_ / BM);   // (49, 8) = 392 blocks
    conv_gemm_kernel<<<grid, 256>>>(x, (float*)d_out);
}